// round 2
// baseline (speedup 1.0000x reference)
#include <cuda_runtime.h>
#include <cuda_bf16.h>

// NBVLoss: weighted BCE full reduction, single fused kernel.
//   loss = 1.6 * sum_{t==1} bce + 0.4 * sum_{t==0} bce
//   bce  = -(t*max(log p, -100) + (1-t)*max(log(1-p), -100))
// Per-block double partials; the last block to finish reduces them in a
// fixed order (deterministic) and resets the arrival counter for replay.

constexpr int BLOCKS  = 1184;   // 148 SMs * 8 CTAs
constexpr int THREADS = 256;
constexpr float LOG_CLAMP = -100.0f;

__device__ double g_partial[BLOCKS];
__device__ unsigned int g_arrive_count;   // zero-init; reset by last block

__device__ __forceinline__ float bce_w(float p, float t) {
    // __logf(0) = -inf -> clamped to -100, matching jnp.clip(log(p), -100)
    float lp = fmaxf(__logf(p),        LOG_CLAMP);
    float lq = fmaxf(__logf(1.0f - p), LOG_CLAMP);
    // t is exactly 0.0f or 1.0f
    return -(1.6f * t * lp + 0.4f * (1.0f - t) * lq);
}

__global__ void __launch_bounds__(THREADS)
bce_fused_kernel(const float4* __restrict__ pred,
                 const float4* __restrict__ targ,
                 int n4, int n_tail_base, int n_total,
                 float* __restrict__ out)
{
    float local = 0.0f;

    int idx = blockIdx.x * THREADS + threadIdx.x;
    const int stride = BLOCKS * THREADS;
    #pragma unroll 4
    for (; idx < n4; idx += stride) {
        float4 pv = pred[idx];
        float4 tv = targ[idx];
        local += bce_w(pv.x, tv.x);
        local += bce_w(pv.y, tv.y);
        local += bce_w(pv.z, tv.z);
        local += bce_w(pv.w, tv.w);
    }

    // Scalar tail (n not divisible by 4) — one thread, deterministic.
    if (blockIdx.x == 0 && threadIdx.x == 0) {
        const float* ps = (const float*)pred;
        const float* ts = (const float*)targ;
        for (int i = n_tail_base; i < n_total; i++)
            local += bce_w(ps[i], ts[i]);
    }

    // Warp reduce (float), then cross-warp in double (fixed order per block).
    #pragma unroll
    for (int off = 16; off > 0; off >>= 1)
        local += __shfl_down_sync(0xFFFFFFFFu, local, off);

    __shared__ double s_warp[THREADS / 32];
    __shared__ bool s_is_last;
    int wid = threadIdx.x >> 5;
    int lid = threadIdx.x & 31;
    if (lid == 0) s_warp[wid] = (double)local;
    __syncthreads();

    if (threadIdx.x == 0) {
        double acc = 0.0;
        #pragma unroll
        for (int w = 0; w < THREADS / 32; w++) acc += s_warp[w];
        g_partial[blockIdx.x] = acc;
        // Make the partial globally visible before signaling arrival.
        __threadfence();
        unsigned int prev = atomicAdd(&g_arrive_count, 1u);
        s_is_last = (prev == (unsigned int)(BLOCKS - 1));
    }
    __syncthreads();

    if (s_is_last) {
        // Last block reduces all partials in a FIXED order -> deterministic.
        __shared__ double s_fin[THREADS];
        double v = 0.0;
        for (int i = threadIdx.x; i < BLOCKS; i += THREADS)
            v += g_partial[i];
        s_fin[threadIdx.x] = v;
        __syncthreads();
        #pragma unroll
        for (int off = THREADS / 2; off > 0; off >>= 1) {
            if (threadIdx.x < off) s_fin[threadIdx.x] += s_fin[threadIdx.x + off];
            __syncthreads();
        }
        if (threadIdx.x == 0) {
            out[0] = (float)s_fin[0];
            g_arrive_count = 0;   // reset for next graph replay
        }
    }
}

extern "C" void kernel_launch(void* const* d_in, const int* in_sizes, int n_in,
                              void* d_out, int out_size)
{
    const float4* pred = (const float4*)d_in[0];
    const float4* targ = (const float4*)d_in[1];
    float* out = (float*)d_out;

    int n  = in_sizes[0];        // 16384*4096 = 67108864
    int n4 = n >> 2;
    int tail_base = n4 << 2;

    bce_fused_kernel<<<BLOCKS, THREADS>>>(pred, targ, n4, tail_base, n, out);
}

// round 3
// speedup vs baseline: 1.2009x; 1.2009x over previous
#include <cuda_runtime.h>
#include <cuda_bf16.h>

// NBVLoss: weighted BCE full reduction, single fused kernel.
//   loss = 1.6 * sum_{t==1} bce + 0.4 * sum_{t==0} bce
//   bce  = -(t*max(log p, -100) + (1-t)*max(log(1-p), -100))
// Per-block double partials; the last block to finish reduces them in a
// fixed order (deterministic) and resets the arrival counter for replay.
//
// __launch_bounds__(256, 8) is load-bearing: it caps regs at 32/thread so
// exactly 8 CTAs/SM are resident -> grid 1184 = ONE wave on 148 SMs.
// (R2 post-mortem: unroll-4 pushed regs to 36 -> 7 CTAs/SM -> straggler
// second wave -> +16us.)

constexpr int BLOCKS  = 1184;   // 148 SMs * 8 CTAs
constexpr int THREADS = 256;
constexpr float LOG_CLAMP = -100.0f;

__device__ double g_partial[BLOCKS];
__device__ unsigned int g_arrive_count;   // zero-init; reset by last block

__device__ __forceinline__ float bce_w(float p, float t) {
    // __logf(0) = -inf -> clamped to -100, matching jnp.clip(log(p), -100)
    float lp = fmaxf(__logf(p),        LOG_CLAMP);
    float lq = fmaxf(__logf(1.0f - p), LOG_CLAMP);
    // t is exactly 0.0f or 1.0f
    return -(1.6f * t * lp + 0.4f * (1.0f - t) * lq);
}

__global__ void __launch_bounds__(THREADS, 8)
bce_fused_kernel(const float4* __restrict__ pred,
                 const float4* __restrict__ targ,
                 int n4, int n_tail_base, int n_total,
                 float* __restrict__ out)
{
    float local = 0.0f;

    int idx = blockIdx.x * THREADS + threadIdx.x;
    const int stride = BLOCKS * THREADS;
    for (; idx < n4; idx += stride) {
        float4 pv = pred[idx];
        float4 tv = targ[idx];
        local += bce_w(pv.x, tv.x);
        local += bce_w(pv.y, tv.y);
        local += bce_w(pv.z, tv.z);
        local += bce_w(pv.w, tv.w);
    }

    // Scalar tail (n not divisible by 4) — one thread, deterministic.
    if (blockIdx.x == 0 && threadIdx.x == 0) {
        const float* ps = (const float*)pred;
        const float* ts = (const float*)targ;
        for (int i = n_tail_base; i < n_total; i++)
            local += bce_w(ps[i], ts[i]);
    }

    // Warp reduce (float), then cross-warp in double (fixed order per block).
    #pragma unroll
    for (int off = 16; off > 0; off >>= 1)
        local += __shfl_down_sync(0xFFFFFFFFu, local, off);

    __shared__ double s_warp[THREADS / 32];
    __shared__ bool s_is_last;
    int wid = threadIdx.x >> 5;
    int lid = threadIdx.x & 31;
    if (lid == 0) s_warp[wid] = (double)local;
    __syncthreads();

    if (threadIdx.x == 0) {
        double acc = 0.0;
        #pragma unroll
        for (int w = 0; w < THREADS / 32; w++) acc += s_warp[w];
        g_partial[blockIdx.x] = acc;
        // Make the partial globally visible before signaling arrival.
        __threadfence();
        unsigned int prev = atomicAdd(&g_arrive_count, 1u);
        s_is_last = (prev == (unsigned int)(BLOCKS - 1));
    }
    __syncthreads();

    if (s_is_last) {
        // Last block reduces all partials in a FIXED order -> deterministic.
        __shared__ double s_fin[THREADS];
        double v = 0.0;
        for (int i = threadIdx.x; i < BLOCKS; i += THREADS)
            v += g_partial[i];
        s_fin[threadIdx.x] = v;
        __syncthreads();
        #pragma unroll
        for (int off = THREADS / 2; off > 0; off >>= 1) {
            if (threadIdx.x < off) s_fin[threadIdx.x] += s_fin[threadIdx.x + off];
            __syncthreads();
        }
        if (threadIdx.x == 0) {
            out[0] = (float)s_fin[0];
            g_arrive_count = 0;   // reset for next graph replay
        }
    }
}

extern "C" void kernel_launch(void* const* d_in, const int* in_sizes, int n_in,
                              void* d_out, int out_size)
{
    const float4* pred = (const float4*)d_in[0];
    const float4* targ = (const float4*)d_in[1];
    float* out = (float*)d_out;

    int n  = in_sizes[0];        // 16384*4096 = 67108864
    int n4 = n >> 2;
    int tail_base = n4 << 2;

    bce_fused_kernel<<<BLOCKS, THREADS>>>(pred, targ, n4, tail_base, n, out);
}

// round 4
// speedup vs baseline: 1.2337x; 1.0273x over previous
#include <cuda_runtime.h>
#include <cuda_bf16.h>

// NBVLoss: weighted BCE full reduction, single fused kernel.
//   loss = 1.6 * sum_{t==1} bce + 0.4 * sum_{t==0} bce
//   bce  = -(t*max(log p, -100) + (1-t)*max(log(1-p), -100))
//
// Key algebraic simplification: t is exactly 0 or 1, so each element needs
// ONE log: contrib = -w * max(__logf(x), -100) with (x,w) = t ? (p,1.6)
// : (1-p,0.4).  Halves MUFU pressure vs computing both log terms.
//
// Per-block double partials; the last block to finish reduces them in a
// fixed order (deterministic) and resets the arrival counter for replay.
//
// __launch_bounds__(256, 8) is load-bearing: caps regs at 32/thread so
// 8 CTAs/SM are resident -> grid 1184 = ONE wave on 148 SMs.

constexpr int BLOCKS  = 1184;   // 148 SMs * 8 CTAs
constexpr int THREADS = 256;
constexpr float LOG_CLAMP = -100.0f;

__device__ double g_partial[BLOCKS];
__device__ unsigned int g_arrive_count;   // zero-init; reset by last block

__device__ __forceinline__ float bce_w(float p, float t) {
    bool one = (t != 0.0f);
    float x = one ? p    : (1.0f - p);
    float w = one ? 1.6f : 0.4f;
    // __logf(0) = -inf -> clamped to -100, matching jnp.clip(log(.), -100)
    float lx = fmaxf(__logf(x), LOG_CLAMP);
    return -w * lx;
}

__global__ void __launch_bounds__(THREADS, 8)
bce_fused_kernel(const float4* __restrict__ pred,
                 const float4* __restrict__ targ,
                 int n4, int n_tail_base, int n_total,
                 float* __restrict__ out)
{
    float local = 0.0f;

    int idx = blockIdx.x * THREADS + threadIdx.x;
    const int stride = BLOCKS * THREADS;
    for (; idx < n4; idx += stride) {
        float4 pv = __ldcs(&pred[idx]);   // streaming: read-once data
        float4 tv = __ldcs(&targ[idx]);
        local += bce_w(pv.x, tv.x);
        local += bce_w(pv.y, tv.y);
        local += bce_w(pv.z, tv.z);
        local += bce_w(pv.w, tv.w);
    }

    // Scalar tail (n not divisible by 4) — one thread, deterministic.
    if (blockIdx.x == 0 && threadIdx.x == 0) {
        const float* ps = (const float*)pred;
        const float* ts = (const float*)targ;
        for (int i = n_tail_base; i < n_total; i++)
            local += bce_w(ps[i], ts[i]);
    }

    // Warp reduce (float), then cross-warp in double (fixed order per block).
    #pragma unroll
    for (int off = 16; off > 0; off >>= 1)
        local += __shfl_down_sync(0xFFFFFFFFu, local, off);

    __shared__ double s_warp[THREADS / 32];
    __shared__ bool s_is_last;
    int wid = threadIdx.x >> 5;
    int lid = threadIdx.x & 31;
    if (lid == 0) s_warp[wid] = (double)local;
    __syncthreads();

    if (threadIdx.x == 0) {
        double acc = 0.0;
        #pragma unroll
        for (int w = 0; w < THREADS / 32; w++) acc += s_warp[w];
        g_partial[blockIdx.x] = acc;
        // Make the partial globally visible before signaling arrival.
        __threadfence();
        unsigned int prev = atomicAdd(&g_arrive_count, 1u);
        s_is_last = (prev == (unsigned int)(BLOCKS - 1));
    }
    __syncthreads();

    if (s_is_last) {
        // Last block reduces all partials in a FIXED order -> deterministic.
        __shared__ double s_fin[THREADS];
        double v = 0.0;
        for (int i = threadIdx.x; i < BLOCKS; i += THREADS)
            v += g_partial[i];
        s_fin[threadIdx.x] = v;
        __syncthreads();
        #pragma unroll
        for (int off = THREADS / 2; off > 0; off >>= 1) {
            if (threadIdx.x < off) s_fin[threadIdx.x] += s_fin[threadIdx.x + off];
            __syncthreads();
        }
        if (threadIdx.x == 0) {
            out[0] = (float)s_fin[0];
            g_arrive_count = 0;   // reset for next graph replay
        }
    }
}

extern "C" void kernel_launch(void* const* d_in, const int* in_sizes, int n_in,
                              void* d_out, int out_size)
{
    const float4* pred = (const float4*)d_in[0];
    const float4* targ = (const float4*)d_in[1];
    float* out = (float*)d_out;

    int n  = in_sizes[0];        // 16384*4096 = 67108864
    int n4 = n >> 2;
    int tail_base = n4 << 2;

    bce_fused_kernel<<<BLOCKS, THREADS>>>(pred, targ, n4, tail_base, n, out);
}